// round 17
// baseline (speedup 1.0000x reference)
#include <cuda_runtime.h>
#include <cuda_bf16.h>
#include <cstdint>
#include <math.h>

#define BB   2
#define SS   2048
#define DD   1024
#define HH   16
#define HDIM 64
#define MTOT (BB*SS)   // 4096
#define XSZ  (MTOT*DD) // 4M elems
#define WSZ  (DD*DD)   // 1M elems

// ---------------- scratch (__device__ globals; device-side refs ONLY) ------
__device__ __align__(16) __nv_bfloat16 g_axhi[3*XSZ];   // q,k,v input splits
__device__ __align__(16) __nv_bfloat16 g_axlo[3*XSZ];
__device__ __align__(16) __nv_bfloat16 g_w2hi[4*WSZ];   // wq,wk,wv,wo splits
__device__ __align__(16) __nv_bfloat16 g_w2lo[4*WSZ];
__device__ __align__(16) __nv_bfloat16 g_qhi[BB*HH*SS*HDIM];
__device__ __align__(16) __nv_bfloat16 g_khi[BB*HH*SS*HDIM];
__device__ __align__(16) __nv_bfloat16 g_vhi[BB*HH*SS*HDIM];
__device__ __align__(16) __nv_bfloat16 g_vlo[BB*HH*SS*HDIM];
__device__ __align__(16) __nv_bfloat16 g_xhi[XSZ];      // ctx from flash
__device__ __align__(16) __nv_bfloat16 g_xlo[XSZ];

// ---------------- helpers ---------------------------------------------------
__device__ __forceinline__ void mma16816(float* c, const uint32_t* a, const uint32_t* b) {
    asm volatile(
        "mma.sync.aligned.m16n8k16.row.col.f32.bf16.bf16.f32 "
        "{%0,%1,%2,%3},{%4,%5,%6,%7},{%8,%9},{%0,%1,%2,%3};"
        : "+f"(c[0]), "+f"(c[1]), "+f"(c[2]), "+f"(c[3])
        : "r"(a[0]), "r"(a[1]), "r"(a[2]), "r"(a[3]), "r"(b[0]), "r"(b[1]));
}

// ldmatrix x2 with on-the-fly transpose (b16): delivers fragment of tile^T
// in the standard (lane l -> r=l>>2, c=2(l&3)) convention.
__device__ __forceinline__ void ldsm_x2_trans(uint32_t* r, uint32_t addr) {
    asm volatile("ldmatrix.sync.aligned.m8n8.x2.trans.shared.b16 {%0,%1}, [%2];"
        : "=r"(r[0]), "=r"(r[1]) : "r"(addr));
}

__device__ __forceinline__ uint32_t pack_bf16x2(float lo, float hi) {
    uint32_t d;
    asm("cvt.rn.bf16x2.f32 %0, %1, %2;" : "=r"(d) : "f"(hi), "f"(lo));
    return d;
}
__device__ __forceinline__ void split_pair(float x, float y, uint32_t& ph, uint32_t& pl) {
    ph = pack_bf16x2(x, y);
    float tx = __uint_as_float(ph << 16);
    float ty = __uint_as_float(ph & 0xFFFF0000u);
    pl = pack_bf16x2(x - tx, y - ty);
}

// fast 2^f via FMA (no MUFU). f <= ~1, clamped at -80.
__device__ __forceinline__ float fast_exp2(float f) {
    f = fmaxf(f, -80.0f);
    float t2 = f + 12582912.0f;
    float r  = f - (t2 - 12582912.0f);
    float p  = 1.0f + r * (0.69314718f + r * (0.24022651f +
                   r * (0.05550411f + r * 0.00961813f)));
    uint32_t eb = (__float_as_uint(t2) << 23) - (0x4B400000u << 23);
    return __uint_as_float(__float_as_uint(p) + eb);
}

__device__ __forceinline__ uint32_t smem_u32(const void* p) {
    uint32_t a;
    asm("{ .reg .u64 t; cvta.to.shared.u64 t, %1; cvt.u32.u64 %0, t; }"
        : "=r"(a) : "l"(p));
    return a;
}
#define CP_ASYNC16(dst, src) \
    asm volatile("cp.async.cg.shared.global [%0], [%1], 16;" \
        :: "r"(dst), "l"(src) : "memory")
#define CP_COMMIT() asm volatile("cp.async.commit_group;" ::: "memory")
#define CP_WAIT0()  asm volatile("cp.async.wait_group 0;" ::: "memory")
#define CP_WAIT1()  asm volatile("cp.async.wait_group 1;" ::: "memory")

// ---------------- bf16 split conversions ------------------------------------
__device__ __forceinline__ void split4(float4 v, uint2& hi, uint2& lo) {
    __nv_bfloat16 h0 = __float2bfloat16(v.x), h1 = __float2bfloat16(v.y);
    __nv_bfloat16 h2 = __float2bfloat16(v.z), h3 = __float2bfloat16(v.w);
    __nv_bfloat16 l0 = __float2bfloat16(v.x - __bfloat162float(h0));
    __nv_bfloat16 l1 = __float2bfloat16(v.y - __bfloat162float(h1));
    __nv_bfloat16 l2 = __float2bfloat16(v.z - __bfloat162float(h2));
    __nv_bfloat16 l3 = __float2bfloat16(v.w - __bfloat162float(h3));
    hi.x = ((uint32_t)__bfloat16_as_ushort(h1) << 16) | __bfloat16_as_ushort(h0);
    hi.y = ((uint32_t)__bfloat16_as_ushort(h3) << 16) | __bfloat16_as_ushort(h2);
    lo.x = ((uint32_t)__bfloat16_as_ushort(l1) << 16) | __bfloat16_as_ushort(l0);
    lo.y = ((uint32_t)__bfloat16_as_ushort(l3) << 16) | __bfloat16_as_ushort(l2);
}

__global__ __launch_bounds__(256) void convert_act(
    const float* __restrict__ Q, const float* __restrict__ K,
    const float* __restrict__ V, int n4)
{
    int i = blockIdx.x * blockDim.x + threadIdx.x;
    if (i >= n4) return;
    int z = blockIdx.y;
    const float* src = (z == 0) ? Q : (z == 1) ? K : V;
    size_t off = (size_t)z * (XSZ / 4);
    uint2 h, l;
    split4(((const float4*)src)[i], h, l);
    ((uint2*)g_axhi)[off + i] = h;
    ((uint2*)g_axlo)[off + i] = l;
}

__global__ __launch_bounds__(256) void convert_w(
    const float* __restrict__ Wq, const float* __restrict__ Wk,
    const float* __restrict__ Wv, const float* __restrict__ Wo, int n4)
{
    int i = blockIdx.x * blockDim.x + threadIdx.x;
    if (i >= n4) return;
    int z = blockIdx.y;
    const float* src = (z == 0) ? Wq : (z == 1) ? Wk : (z == 2) ? Wv : Wo;
    size_t off = (size_t)z * (WSZ / 4);
    uint2 h, l;
    split4(((const float4*)src)[i], h, l);
    ((uint2*)g_w2hi)[off + i] = h;
    ((uint2*)g_w2lo)[off + i] = l;
}

// ---------------- GEMM core (proven R14): pass-major, K=64 double-buffer ---
#define GROWB 144
#define MATB  (128*GROWB)     // 18432
#define STG2  (2*MATB)        // 36864 per stage
#define SMEM_G2 (2*STG2)      // 73728

__device__ __forceinline__ void p_fill(
    uint32_t sb, int buf, int c, int tid, int m0, int n0,
    const __nv_bfloat16* __restrict__ Ahi, const __nv_bfloat16* __restrict__ Alo,
    const __nv_bfloat16* __restrict__ Bhi, const __nv_bfloat16* __restrict__ Blo)
{
    const int p  = c >> 4;
    const int kc = (c & 15) * 64;
    const __nv_bfloat16* A = (p < 2)  ? Ahi : Alo;
    const __nv_bfloat16* B = (p == 1) ? Blo : Bhi;
    const uint32_t st = sb + buf * STG2;
    #pragma unroll
    for (int i = 0; i < 4; i++) {
        int t = tid + i * 256;
        int row = t >> 3, g = t & 7;
        uint32_t d = row * GROWB + g * 16;
        CP_ASYNC16(st +        d, (const void*)(A + (size_t)(m0 + row) * DD + kc + g * 8));
        CP_ASYNC16(st + MATB + d, (const void*)(B + (size_t)(n0 + row) * DD + kc + g * 8));
    }
}

__device__ __forceinline__ void gemm_core(
    float acc[4][4][4], char* smp, uint32_t sb, int tid, int wr, int wc, int lid,
    int m0, int n0,
    const __nv_bfloat16* __restrict__ Ahi, const __nv_bfloat16* __restrict__ Alo,
    const __nv_bfloat16* __restrict__ Bhi, const __nv_bfloat16* __restrict__ Blo)
{
    p_fill(sb, 0, 0, tid, m0, n0, Ahi, Alo, Bhi, Blo);
    CP_COMMIT();

    for (int c = 0; c < 48; c++) {
        const int buf = c & 1;
        if (c + 1 < 48) {
            p_fill(sb, buf ^ 1, c + 1, tid, m0, n0, Ahi, Alo, Bhi, Blo);
            CP_COMMIT();
            CP_WAIT1();
        } else {
            CP_WAIT0();
        }
        __syncthreads();

        const char* stg = smp + buf * STG2;
        #pragma unroll
        for (int st = 0; st < 4; st++) {
            const int kbyte = st * 32 + (lid & 3) * 4;
            uint32_t af[4][4], bf[4][2];
            #pragma unroll
            for (int mt = 0; mt < 4; mt++) {
                const char* base = stg +
                    (wr * 64 + mt * 16 + (lid >> 2)) * GROWB + kbyte;
                af[mt][0] = *(const uint32_t*)(base);
                af[mt][1] = *(const uint32_t*)(base + 8 * GROWB);
                af[mt][2] = *(const uint32_t*)(base + 16);
                af[mt][3] = *(const uint32_t*)(base + 8 * GROWB + 16);
            }
            #pragma unroll
            for (int nt = 0; nt < 4; nt++) {
                const char* base = stg + MATB +
                    (wc * 32 + nt * 8 + (lid >> 2)) * GROWB + kbyte;
                bf[nt][0] = *(const uint32_t*)(base);
                bf[nt][1] = *(const uint32_t*)(base + 16);
            }
            #pragma unroll
            for (int mt = 0; mt < 4; mt++)
                #pragma unroll
                for (int nt = 0; nt < 4; nt++)
                    mma16816(acc[mt][nt], af[mt], bf[nt]);
        }
        __syncthreads();
    }
}

__global__ __launch_bounds__(256) void proj_tc(
    const float* __restrict__ bq, const float* __restrict__ bk,
    const float* __restrict__ bv)
{
    extern __shared__ __align__(16) char sm[];
    const int tid = threadIdx.x, wid = tid >> 5, lid = tid & 31;
    const int n0 = blockIdx.x * 128, m0 = blockIdx.y * 128;
    const int z  = blockIdx.z;
    const int wr = wid & 1, wc = wid >> 1;
    const uint32_t sb = smem_u32(sm);

    const __nv_bfloat16* Ahi = g_axhi + (size_t)z * XSZ;
    const __nv_bfloat16* Alo = g_axlo + (size_t)z * XSZ;
    const __nv_bfloat16* Bhi = g_w2hi + (size_t)z * WSZ;
    const __nv_bfloat16* Blo = g_w2lo + (size_t)z * WSZ;
    const float* bias = (z == 0) ? bq : (z == 1) ? bk : bv;

    float acc[4][4][4] = {};
    gemm_core(acc, sm, sb, tid, wr, wc, lid, m0, n0, Ahi, Alo, Bhi, Blo);

    #pragma unroll
    for (int mt = 0; mt < 4; mt++) {
        #pragma unroll
        for (int nt = 0; nt < 4; nt++) {
            int col = n0 + wc * 32 + nt * 8 + (lid & 3) * 2;
            float2 bvv = *(const float2*)(bias + col);
            int r0 = m0 + wr * 64 + mt * 16 + (lid >> 2);
            #pragma unroll
            for (int half = 0; half < 2; half++) {
                int r = r0 + half * 8;
                float ox = acc[mt][nt][half * 2 + 0] + bvv.x;
                float oy = acc[mt][nt][half * 2 + 1] + bvv.y;
                int b = r >> 11, s = r & (SS - 1);
                int hh = col >> 6, hd = col & 63;
                size_t off = (((size_t)(b * HH + hh)) * SS + s) * HDIM + hd;
                uint32_t ph, pl;
                split_pair(ox, oy, ph, pl);
                if (z == 0) {
                    *(uint32_t*)(g_qhi + off) = ph;
                } else if (z == 1) {
                    *(uint32_t*)(g_khi + off) = ph;
                } else {
                    *(uint32_t*)(g_vhi + off) = ph;
                    *(uint32_t*)(g_vlo + off) = pl;
                }
            }
        }
    }
}

__global__ __launch_bounds__(256) void oproj_tc(
    const float* __restrict__ bias, float* __restrict__ outp)
{
    extern __shared__ __align__(16) char sm[];
    const int tid = threadIdx.x, wid = tid >> 5, lid = tid & 31;
    const int n0 = blockIdx.x * 128, m0 = blockIdx.y * 128;
    const int wr = wid & 1, wc = wid >> 1;
    const uint32_t sb = smem_u32(sm);

    float acc[4][4][4] = {};
    gemm_core(acc, sm, sb, tid, wr, wc, lid, m0, n0,
              g_xhi, g_xlo, g_w2hi + 3 * (size_t)WSZ, g_w2lo + 3 * (size_t)WSZ);

    #pragma unroll
    for (int mt = 0; mt < 4; mt++) {
        #pragma unroll
        for (int nt = 0; nt < 4; nt++) {
            int col = n0 + wc * 32 + nt * 8 + (lid & 3) * 2;
            float2 bvv = *(const float2*)(bias + col);
            int r0 = m0 + wr * 64 + mt * 16 + (lid >> 2);
            #pragma unroll
            for (int half = 0; half < 2; half++) {
                int r = r0 + half * 8;
                float2 o;
                o.x = acc[mt][nt][half * 2 + 0] + bvv.x;
                o.y = acc[mt][nt][half * 2 + 1] + bvv.y;
                *(float2*)(outp + (size_t)r * DD + col) = o;
            }
        }
    }
}

// ---------------- flash attention: pipelined fills + ldmatrix.trans V ------
// kt-chunk 64. V stored NATURALLY [kt][d] (cp.async, no transpose); PV
// B-fragments produced by ldmatrix.m8n8.x2.trans.
// Stage = K(64x64) + Vhi + Vlo, each 64 rows x 144B = 27648 B; x2 stages.
#define QROWB 144
#define VROWN 144
#define KSTG_B  (64*QROWB)          // 9216
#define STG_VH  KSTG_B
#define STG_VL  (2*KSTG_B)
#define FSTG_B  (3*KSTG_B)          // 27648
#define OFF_STG 18432               // after Q tile
#define SMEM_FLASH (OFF_STG + 2*FSTG_B)  // 73728

__global__ __launch_bounds__(256, 2) void flash_mma()
{
    extern __shared__ __align__(16) char sm[];
    const int tid = threadIdx.x, wid = tid >> 5, lid = tid & 31;
    const int q0 = blockIdx.x * 128, h = blockIdx.y, b = blockIdx.z;
    const size_t base = ((size_t)(b * HH + h)) * SS * HDIM;
    const uint32_t sb = smem_u32(sm);
    const float cf = 0.18033688f;   // 0.125 * log2(e)

    // Q tile 128x64 (hi only), full 128B rows via uint4
    #pragma unroll
    for (int i = 0; i < 4; i++) {
        int idx = tid + i * 256, row = idx >> 3, g = idx & 7;
        size_t src = base + (size_t)(q0 + row) * HDIM + g * 8;
        *(uint4*)(sm + row * QROWB + g * 16) = *(const uint4*)(g_qhi + src);
    }

    // fill one kt-chunk (c) into stage buf: K + Vhi + Vlo, all cp.async
    const int f_row = tid >> 3, f_g = tid & 7;   // 32 rows x 8 groups per iter
    auto fchunk = [&](int c, int buf) {
        uint32_t st = sb + OFF_STG + buf * FSTG_B;
        int kt0 = c * 64;
        #pragma unroll
        for (int i = 0; i < 2; i++) {
            int row = f_row + i * 32;
            size_t src = base + (size_t)(kt0 + row) * HDIM + f_g * 8;
            uint32_t d = row * QROWB + f_g * 16;
            CP_ASYNC16(st +          d, (const void*)(g_khi + src));
            CP_ASYNC16(st + STG_VH + d, (const void*)(g_vhi + src));
            CP_ASYNC16(st + STG_VL + d, (const void*)(g_vlo + src));
        }
    };

    fchunk(0, 0);
    CP_COMMIT();
    __syncthreads();   // Q visible

    uint32_t aQh[4][4];
    const int qrb = (wid * 16 + (lid >> 2)) * QROWB + (lid & 3) * 4;
    #pragma unroll
    for (int ks = 0; ks < 4; ks++) {
        const char* p = sm + qrb + ks * 32;
        aQh[ks][0] = *(const uint32_t*)(p);
        aQh[ks][1] = *(const uint32_t*)(p + 8 * QROWB);
        aQh[ks][2] = *(const uint32_t*)(p + 16);
        aQh[ks][3] = *(const uint32_t*)(p + 8 * QROWB + 16);
    }

    float acc[8][4] = {};
    float mrow[2] = {-1e30f, -1e30f}, lrow[2] = {0.f, 0.f};

    const uint32_t vlane = (lid & 15) * VROWN;

    for (int c = 0; c < 32; c++) {
        const int buf = c & 1;
        if (c + 1 < 32) {
            fchunk(c + 1, buf ^ 1);
            CP_COMMIT();
            CP_WAIT1();
        } else {
            CP_WAIT0();
        }
        __syncthreads();   // fill(c) visible; prior compute done via trailing sync

        const char* stK = sm + OFF_STG + buf * FSTG_B;
        const uint32_t stVh = sb + OFF_STG + buf * FSTG_B + STG_VH;
        const uint32_t stVl = sb + OFF_STG + buf * FSTG_B + STG_VL;

        // S = Qhi Khi^T (single pass), 8 n-tiles x 4 k-steps
        float sf[8][4];
        #pragma unroll
        for (int nt = 0; nt < 8; nt++)
            sf[nt][0] = sf[nt][1] = sf[nt][2] = sf[nt][3] = 0.f;
        #pragma unroll
        for (int nt = 0; nt < 8; nt++) {
            #pragma unroll
            for (int ks = 0; ks < 4; ks++) {
                const char* p = stK +
                    (nt * 8 + (lid >> 2)) * QROWB + ks * 32 + (lid & 3) * 4;
                uint32_t bf[2] = { *(const uint32_t*)p, *(const uint32_t*)(p + 16) };
                mma16816(sf[nt], aQh[ks], bf);
            }
        }

        // online softmax
        float corr[2];
        #pragma unroll
        for (int half = 0; half < 2; half++) {
            const int v0 = half * 2, v1 = half * 2 + 1;
            float tm = -1e30f;
            #pragma unroll
            for (int nt = 0; nt < 8; nt++)
                tm = fmaxf(tm, fmaxf(sf[nt][v0], sf[nt][v1]));
            tm = fmaxf(tm, __shfl_xor_sync(0xffffffffu, tm, 1));
            tm = fmaxf(tm, __shfl_xor_sync(0xffffffffu, tm, 2));
            float mn = fmaxf(mrow[half], tm * cf);
            corr[half] = fast_exp2(mrow[half] - mn);
            mrow[half] = mn;
            float sum = 0.f;
            #pragma unroll
            for (int nt = 0; nt < 8; nt++) {
                float p0 = fast_exp2(fmaf(sf[nt][v0], cf, -mn));
                float p1 = fast_exp2(fmaf(sf[nt][v1], cf, -mn));
                sf[nt][v0] = p0; sf[nt][v1] = p1;
                sum += p0 + p1;
            }
            sum += __shfl_xor_sync(0xffffffffu, sum, 1);
            sum += __shfl_xor_sync(0xffffffffu, sum, 2);
            lrow[half] = lrow[half] * corr[half] + sum;
        }
        #pragma unroll
        for (int nt = 0; nt < 8; nt++) {
            acc[nt][0] *= corr[0]; acc[nt][1] *= corr[0];
            acc[nt][2] *= corr[1]; acc[nt][3] *= corr[1];
        }

        // PV: ks-fused P pack + ldmatrix.trans V fragments (natural layout)
        #pragma unroll
        for (int ks = 0; ks < 4; ks++) {
            uint32_t aPh[4], aPl[4];
            split_pair(sf[2*ks  ][0], sf[2*ks  ][1], aPh[0], aPl[0]);
            split_pair(sf[2*ks  ][2], sf[2*ks  ][3], aPh[1], aPl[1]);
            split_pair(sf[2*ks+1][0], sf[2*ks+1][1], aPh[2], aPl[2]);
            split_pair(sf[2*ks+1][2], sf[2*ks+1][3], aPh[3], aPl[3]);
            const uint32_t koff = ks * 16 * VROWN + vlane;
            #pragma unroll
            for (int nt = 0; nt < 8; nt++) {
                uint32_t bh[2], bl[2];
                ldsm_x2_trans(bh, stVh + koff + nt * 16);
                ldsm_x2_trans(bl, stVl + koff + nt * 16);
                mma16816(acc[nt], aPh, bh);
                mma16816(acc[nt], aPl, bh);
                mma16816(acc[nt], aPh, bl);
            }
        }
        __syncthreads();   // all warps done with buf before refill at c+1
    }

    // epilogue: normalize, split, write ctx hi/lo row-major [M, D]
    float inv0 = 1.0f / lrow[0], inv1 = 1.0f / lrow[1];
    int r0 = q0 + wid * 16 + (lid >> 2);
    size_t m0 = (size_t)(b * SS + r0) * DD + h * HDIM;
    #pragma unroll
    for (int nt = 0; nt < 8; nt++) {
        int d = nt * 8 + 2 * (lid & 3);
        uint32_t ph, pl;
        split_pair(acc[nt][0] * inv0, acc[nt][1] * inv0, ph, pl);
        *(uint32_t*)(g_xhi + m0 + d) = ph;
        *(uint32_t*)(g_xlo + m0 + d) = pl;
        split_pair(acc[nt][2] * inv1, acc[nt][3] * inv1, ph, pl);
        *(uint32_t*)(g_xhi + m0 + 8 * DD + d) = ph;
        *(uint32_t*)(g_xlo + m0 + 8 * DD + d) = pl;
    }
}

// ---------------------------------------------------------------------------
extern "C" void kernel_launch(void* const* d_in, const int* in_sizes, int n_in,
                              void* d_out, int out_size)
{
    const float* Q  = (const float*)d_in[0];
    const float* K  = (const float*)d_in[1];
    const float* V  = (const float*)d_in[2];
    const float* Wq = (const float*)d_in[3];
    const float* bq = (const float*)d_in[4];
    const float* Wk = (const float*)d_in[5];
    const float* bk = (const float*)d_in[6];
    const float* Wv = (const float*)d_in[7];
    const float* bv = (const float*)d_in[8];
    const float* Wo = (const float*)d_in[9];
    const float* bo = (const float*)d_in[10];
    float* out = (float*)d_out;

    cudaFuncSetAttribute(proj_tc,   cudaFuncAttributeMaxDynamicSharedMemorySize, SMEM_G2);
    cudaFuncSetAttribute(oproj_tc,  cudaFuncAttributeMaxDynamicSharedMemorySize, SMEM_G2);
    cudaFuncSetAttribute(flash_mma, cudaFuncAttributeMaxDynamicSharedMemorySize, SMEM_FLASH);

    const int x4 = XSZ / 4;
    const int w4 = WSZ / 4;

    convert_act<<<dim3(x4 / 256, 3), 256>>>(Q, K, V, x4);
    convert_w<<<dim3(w4 / 256, 4), 256>>>(Wq, Wk, Wv, Wo, w4);

    proj_tc<<<dim3(DD / 128, MTOT / 128, 3), 256, SMEM_G2>>>(bq, bk, bv);

    flash_mma<<<dim3(SS / 128, HH, BB), 256, SMEM_FLASH>>>();

    oproj_tc<<<dim3(DD / 128, MTOT / 128), 256, SMEM_G2>>>(bo, out);
}